// round 1
// baseline (speedup 1.0000x reference)
#include <cuda_runtime.h>
#include <cuda_bf16.h>
#include <math.h>

// ---------------- problem constants ----------------
#define BATCH 32
#define L0    4096
#define C0    256
#define C1    256
#define C2    512
#define C3    128          // EMB_DIM
#define L1    2048         // after conv1 stride 2
#define L2    1024         // after conv2 stride 2
#define L3    1024         // after conv3 stride 1
#define NEMB  4096
#define NROWS (BATCH * L3) // 32768

// ---------------- scratch (static device globals; no runtime allocs) ----------------
__device__ float g_h1[BATCH * C1 * L1];   // 64 MB
__device__ float g_h2[BATCH * C2 * L2];   // 64 MB
__device__ float g_z [NROWS * C3];        // 16 MB, [row][d]
__device__ float g_znorm[NROWS];
__device__ float g_enorm[NEMB];

// ---------------- fused conv1d(k=3,pad=1) + optional BN(eval) + LeakyReLU ----------------
// Block: NT threads, each thread owns CPT output channels (co = tid + c*NT) and a
// tile of TT consecutive output positions. Input channels streamed through smem
// in chunks of 64. Weights read through L1/L2 (reused TT times per load).
template<int CIN, int COUT, int LIN, int STRIDE, int TT, int CPT, int NT,
         bool BNACT, bool TRANSPOSE_OUT>
__global__ void conv_kernel(const float* __restrict__ x,
                            const float* __restrict__ w,
                            const float* __restrict__ bias,
                            const float* __restrict__ bn_g,
                            const float* __restrict__ bn_b,
                            const float* __restrict__ bn_m,
                            const float* __restrict__ bn_v,
                            float* __restrict__ out)
{
    constexpr int LOUT  = (LIN - 1) / STRIDE + 1;
    constexpr int W     = (TT - 1) * STRIDE + 3;
    constexpr int CHUNK = 64;

    __shared__ float sx[CHUNK][W];

    const int b   = blockIdx.y;
    const int T0  = blockIdx.x * TT;
    const int tid = threadIdx.x;
    const int P0  = T0 * STRIDE - 1;

    float acc[CPT][TT];
#pragma unroll
    for (int c = 0; c < CPT; c++)
#pragma unroll
        for (int t = 0; t < TT; t++) acc[c][t] = 0.0f;

    for (int cc = 0; cc < CIN; cc += CHUNK) {
        __syncthreads();
        const float* xb = x + ((long)b * CIN + cc) * LIN;
        for (int i = tid; i < CHUNK * W; i += NT) {
            int ci = i / W, p = i % W;
            int gp = P0 + p;
            float v = (gp >= 0 && gp < LIN) ? xb[(long)ci * LIN + gp] : 0.0f;
            sx[ci][p] = v;
        }
        __syncthreads();

        for (int ci = 0; ci < CHUNK; ci++) {
#pragma unroll
            for (int c = 0; c < CPT; c++) {
                const int co = tid + c * NT;
                const float* wp = w + ((long)co * CIN + cc + ci) * 3;
                const float w0 = wp[0], w1 = wp[1], w2 = wp[2];
#pragma unroll
                for (int t = 0; t < TT; t++) {
                    float s0 = sx[ci][t * STRIDE + 0];
                    float s1 = sx[ci][t * STRIDE + 1];
                    float s2 = sx[ci][t * STRIDE + 2];
                    acc[c][t] = fmaf(w0, s0, fmaf(w1, s1, fmaf(w2, s2, acc[c][t])));
                }
            }
        }
    }

    // epilogue
#pragma unroll
    for (int c = 0; c < CPT; c++) {
        const int co = tid + c * NT;
        const float bs = bias[co];
        float scale = 1.0f, shift = 0.0f;
        if (BNACT) {
            scale = bn_g[co] / sqrtf(bn_v[co] + 1e-5f);
            shift = bn_b[co] - bn_m[co] * scale;
        }
        if (TRANSPOSE_OUT) {
            // out[(b*LOUT + t)*COUT + co]  (coalesced across threads per t)
            float* ob = out + ((long)b * LOUT + T0) * COUT + co;
#pragma unroll
            for (int t = 0; t < TT; t++) {
                float y = acc[c][t] + bs;
                if (BNACT) {
                    y = y * scale + shift;
                    y = (y >= 0.0f) ? y : 0.01f * y;
                }
                ob[(long)t * COUT] = y;
            }
        } else {
            float* orow = out + ((long)b * COUT + co) * LOUT + T0;
#pragma unroll
            for (int t = 0; t < TT; t += 4) {
                float4 q;
                float y0 = acc[c][t + 0] + bs, y1 = acc[c][t + 1] + bs;
                float y2 = acc[c][t + 2] + bs, y3 = acc[c][t + 3] + bs;
                if (BNACT) {
                    y0 = y0 * scale + shift; y0 = (y0 >= 0.0f) ? y0 : 0.01f * y0;
                    y1 = y1 * scale + shift; y1 = (y1 >= 0.0f) ? y1 : 0.01f * y1;
                    y2 = y2 * scale + shift; y2 = (y2 >= 0.0f) ? y2 : 0.01f * y2;
                    y3 = y3 * scale + shift; y3 = (y3 >= 0.0f) ? y3 : 0.01f * y3;
                }
                q.x = y0; q.y = y1; q.z = y2; q.w = y3;
                *reinterpret_cast<float4*>(orow + t) = q;
            }
        }
    }
}

// ---------------- row squared-norm (one warp per 128-wide row) ----------------
__global__ void rownorm_kernel(const float* __restrict__ src,
                               float* __restrict__ dst, int nrows)
{
    int row  = blockIdx.x * 4 + (threadIdx.x >> 5);
    int lane = threadIdx.x & 31;
    if (row >= nrows) return;
    const float* r = src + (long)row * 128;
    float s = 0.0f;
#pragma unroll
    for (int k = 0; k < 4; k++) {
        float v = r[lane + k * 32];
        s = fmaf(v, v, s);
    }
#pragma unroll
    for (int off = 16; off > 0; off >>= 1)
        s += __shfl_xor_sync(0xffffffffu, s, off);
    if (lane == 0) dst[row] = s;
}

// ---------------- VQ: per 64-row tile, scan all 4096 codes, argmin + gather ----------------
// dist_j replicates reference fp32 expression: (znorm + enorm_j) - 2*dot_j.
// Ties broken by lowest index (jnp.argmin semantics).
__global__ __launch_bounds__(256) void vq_kernel(const float* __restrict__ emb,
                                                 const float* __restrict__ enorm,
                                                 const float* __restrict__ z,
                                                 const float* __restrict__ znorm,
                                                 float* __restrict__ codes_out,
                                                 float* __restrict__ quant_out)
{
    __shared__ float zs[64][129];   // z rows, K=128, padded
    __shared__ float es[64][33];    // emb tile, K-chunk=32, padded
    __shared__ float zns[64];
    __shared__ float ens[64];
    __shared__ int   sidx[64];

    const int tid = threadIdx.x;
    const int tx  = tid & 15;       // N dimension (16 lanes)
    const int ty  = tid >> 4;       // M dimension (16 groups)
    const int M0  = blockIdx.x * 64;

    for (int i = tid; i < 64 * 128; i += 256) {
        int r = i >> 7, k = i & 127;
        zs[r][k] = z[(long)(M0 + r) * 128 + k];
    }
    if (tid < 64) zns[tid] = znorm[M0 + tid];

    float bv[4]; int bi[4];
#pragma unroll
    for (int i = 0; i < 4; i++) { bv[i] = 3.4e38f; bi[i] = 0; }

    for (int N0 = 0; N0 < NEMB; N0 += 64) {
        float c[4][4];
#pragma unroll
        for (int i = 0; i < 4; i++)
#pragma unroll
            for (int j = 0; j < 4; j++) c[i][j] = 0.0f;

        for (int kc = 0; kc < 128; kc += 32) {
            __syncthreads();   // previous consumers done (also covers initial zs fill)
            if (kc == 0 && tid < 64) ens[tid] = enorm[N0 + tid];
            for (int i = tid; i < 64 * 32; i += 256) {
                int n = i >> 5, kk = i & 31;
                es[n][kk] = emb[(long)(N0 + n) * 128 + kc + kk];
            }
            __syncthreads();

#pragma unroll
            for (int kk = 0; kk < 32; kk++) {
                float a0 = zs[ty * 4 + 0][kc + kk];
                float a1 = zs[ty * 4 + 1][kc + kk];
                float a2 = zs[ty * 4 + 2][kc + kk];
                float a3 = zs[ty * 4 + 3][kc + kk];
                float b0 = es[tx * 4 + 0][kk];
                float b1 = es[tx * 4 + 1][kk];
                float b2 = es[tx * 4 + 2][kk];
                float b3 = es[tx * 4 + 3][kk];
                c[0][0] = fmaf(a0, b0, c[0][0]); c[0][1] = fmaf(a0, b1, c[0][1]);
                c[0][2] = fmaf(a0, b2, c[0][2]); c[0][3] = fmaf(a0, b3, c[0][3]);
                c[1][0] = fmaf(a1, b0, c[1][0]); c[1][1] = fmaf(a1, b1, c[1][1]);
                c[1][2] = fmaf(a1, b2, c[1][2]); c[1][3] = fmaf(a1, b3, c[1][3]);
                c[2][0] = fmaf(a2, b0, c[2][0]); c[2][1] = fmaf(a2, b1, c[2][1]);
                c[2][2] = fmaf(a2, b2, c[2][2]); c[2][3] = fmaf(a2, b3, c[2][3]);
                c[3][0] = fmaf(a3, b0, c[3][0]); c[3][1] = fmaf(a3, b1, c[3][1]);
                c[3][2] = fmaf(a3, b2, c[3][2]); c[3][3] = fmaf(a3, b3, c[3][3]);
            }
        }

        // distances + running argmin (j ascending => first-index on ties)
#pragma unroll
        for (int i = 0; i < 4; i++) {
            const float zn = zns[ty * 4 + i];
#pragma unroll
            for (int j = 0; j < 4; j++) {
                float t1 = zn + ens[tx * 4 + j];
                float d  = t1 - 2.0f * c[i][j];
                if (d < bv[i]) { bv[i] = d; bi[i] = N0 + tx * 4 + j; }
            }
        }
    }

    // reduce across the 16 tx lanes that share each row (stay inside half-warp)
#pragma unroll
    for (int i = 0; i < 4; i++) {
#pragma unroll
        for (int off = 8; off > 0; off >>= 1) {
            float ov = __shfl_xor_sync(0xffffffffu, bv[i], off);
            int   oi = __shfl_xor_sync(0xffffffffu, bi[i], off);
            if (ov < bv[i] || (ov == bv[i] && oi < bi[i])) { bv[i] = ov; bi[i] = oi; }
        }
        if (tx == 0) sidx[ty * 4 + i] = bi[i];
    }
    __syncthreads();

    if (codes_out && tid < 64)
        codes_out[M0 + tid] = (float)sidx[tid];
    if (quant_out) {
        for (int i = tid; i < 64 * 128; i += 256) {
            int r = i >> 7, k = i & 127;
            quant_out[(long)(M0 + r) * 128 + k] = emb[(long)sidx[r] * 128 + k];
        }
    }
}

// ---------------- launch ----------------
extern "C" void kernel_launch(void* const* d_in, const int* in_sizes, int n_in,
                              void* d_out, int out_size)
{
    const float* x   = (const float*)d_in[0];
    const float* w1  = (const float*)d_in[1];
    const float* b1  = (const float*)d_in[2];
    const float* g1  = (const float*)d_in[3];
    const float* be1 = (const float*)d_in[4];
    const float* m1  = (const float*)d_in[5];
    const float* v1  = (const float*)d_in[6];
    const float* w2  = (const float*)d_in[7];
    const float* b2  = (const float*)d_in[8];
    const float* g2  = (const float*)d_in[9];
    const float* be2 = (const float*)d_in[10];
    const float* m2  = (const float*)d_in[11];
    const float* v2  = (const float*)d_in[12];
    const float* w3  = (const float*)d_in[13];
    const float* b3  = (const float*)d_in[14];
    const float* emb = (const float*)d_in[15];

    float* h1; float* h2; float* z; float* zn; float* en;
    cudaGetSymbolAddress((void**)&h1, g_h1);
    cudaGetSymbolAddress((void**)&h2, g_h2);
    cudaGetSymbolAddress((void**)&z,  g_z);
    cudaGetSymbolAddress((void**)&zn, g_znorm);
    cudaGetSymbolAddress((void**)&en, g_enorm);

    // output layout: codes [32768] then quantized [4194304] (float32, tuple order).
    float* codes_out = (float*)d_out;
    float* quant_out = (float*)d_out + NROWS;
    if (out_size == NROWS * C3) {            // quantized only
        codes_out = nullptr; quant_out = (float*)d_out;
    } else if (out_size == NROWS) {          // codes only
        quant_out = nullptr;
    }

    // encoder
    conv_kernel<C0, C1, L0, 2, 64, 1, 256, true,  false>
        <<<dim3(L1 / 64, BATCH), 256>>>(x, w1, b1, g1, be1, m1, v1, h1);
    conv_kernel<C1, C2, L1, 2, 32, 2, 256, true,  false>
        <<<dim3(L2 / 32, BATCH), 256>>>(h1, w2, b2, g2, be2, m2, v2, h2);
    conv_kernel<C2, C3, L2, 1, 64, 1, 128, false, true>
        <<<dim3(L3 / 64, BATCH), 128>>>(h2, w3, b3, nullptr, nullptr, nullptr, nullptr, z);

    // norms
    rownorm_kernel<<<NEMB / 4, 128>>>(emb, en, NEMB);
    rownorm_kernel<<<NROWS / 4, 128>>>(z, zn, NROWS);

    // VQ argmin + gather
    vq_kernel<<<NROWS / 64, 256>>>(emb, en, z, zn, codes_out, quant_out);
}

// round 4
// speedup vs baseline: 1.3647x; 1.3647x over previous
#include <cuda_runtime.h>
#include <cuda_bf16.h>
#include <math.h>

// ---------------- problem constants ----------------
#define BATCH 32
#define L0    4096
#define C0    256
#define C1    256
#define C2    512
#define C3    128          // EMB_DIM
#define L1    2048
#define L2    1024
#define L3    1024
#define NEMB  4096
#define NROWS (BATCH * L3) // 32768

// ---------------- scratch ----------------
__device__ float g_h1[BATCH * C1 * L1];     // 64 MB
__device__ float g_h2[BATCH * C2 * L2];     // 64 MB
__device__ float g_z [NROWS * C3];          // 16 MB
__device__ float g_znorm[NROWS];
__device__ float g_enorm[NEMB];
__device__ float g_wt1[C0 * 3 * C1];        // transposed weights [(ci*3+k)][co]
__device__ float g_wt2[C1 * 3 * C2];
__device__ float g_wt3[C2 * 3 * C3];

// ---------------- weight transpose: w[co][ci][k] -> wt[(ci*3+k)][co] ----------------
__global__ void wtrans_kernel(const float* __restrict__ w, float* __restrict__ wt,
                              int CIN, int COUT)
{
    int idx = blockIdx.x * 256 + threadIdx.x;
    int total = CIN * 3 * COUT;
    if (idx < total) {
        int co = idx % COUT;
        int r  = idx / COUT;            // r = ci*3+k
        wt[idx] = w[(long)co * CIN * 3 + r];
    }
}

// ---------------- stride-2 conv + BN(eval) + LeakyReLU ----------------
// Block tile: 64 co x 64 t. Threads 256: tx=co-group(16), ty=t-group(16), 4x4 acc.
// x staged de-interleaved (evens/odds) so taps k=0,1,2 are contiguous in t.
template<int CIN, int COUT, int LIN>
__global__ __launch_bounds__(256) void conv_s2_kernel(
    const float* __restrict__ x, const float* __restrict__ wt,
    const float* __restrict__ bias, const float* __restrict__ bn_g,
    const float* __restrict__ bn_b, const float* __restrict__ bn_m,
    const float* __restrict__ bn_v, float* __restrict__ out)
{
    constexpr int LOUT = LIN / 2;
    constexpr int CC   = 16;

    __shared__ float ev[CC][68];      // ev[ci][u] = x[ci][2*(T0+u)]     u<64
    __shared__ float od[CC][68];      // od[ci][u] = x[ci][2*(T0+u)-1]   u<65
    __shared__ float sw[CC][3][64];   // sw[ci][k][co]

    const int b   = blockIdx.z;
    const int cb  = blockIdx.y * 64;
    const int T0  = blockIdx.x * 64;
    const int tid = threadIdx.x;
    const int tx  = tid & 15;
    const int ty  = tid >> 4;
    const int t0  = ty * 4;
    const int c0  = tx * 4;

    float acc[4][4];
#pragma unroll
    for (int i = 0; i < 4; i++)
#pragma unroll
        for (int j = 0; j < 4; j++) acc[i][j] = 0.0f;

    for (int cc = 0; cc < CIN; cc += CC) {
        __syncthreads();
        const float* xb = x + ((long)b * CIN + cc) * LIN;
        for (int i = tid; i < CC * 64; i += 256) {
            int ci = i >> 6, u = i & 63;
            ev[ci][u] = xb[(long)ci * LIN + 2 * (T0 + u)];
        }
        for (int i = tid; i < CC * 65; i += 256) {
            int ci = i / 65, u = i - ci * 65;
            int p = 2 * (T0 + u) - 1;
            od[ci][u] = (p >= 0) ? xb[(long)ci * LIN + p] : 0.0f;
        }
        for (int i = tid; i < CC * 192; i += 256) {
            int q = i >> 6;                 // q = ci*3+k
            ((float*)sw)[i] = wt[(long)(cc * 3 + q) * COUT + cb + (i & 63)];
        }
        __syncthreads();

#pragma unroll 4
        for (int ci = 0; ci < CC; ci++) {
            float4 aE = *(const float4*)&ev[ci][t0];
            float4 aO = *(const float4*)&od[ci][t0];
            float  oX = od[ci][t0 + 4];
            float4 b0 = *(const float4*)&sw[ci][0][c0];
            float4 b1 = *(const float4*)&sw[ci][1][c0];
            float4 b2 = *(const float4*)&sw[ci][2][c0];
            float a0[4] = {aO.x, aO.y, aO.z, aO.w};          // k=0
            float a1[4] = {aE.x, aE.y, aE.z, aE.w};          // k=1
            float a2[4] = {aO.y, aO.z, aO.w, oX};            // k=2
            float bb0[4] = {b0.x, b0.y, b0.z, b0.w};
            float bb1[4] = {b1.x, b1.y, b1.z, b1.w};
            float bb2[4] = {b2.x, b2.y, b2.z, b2.w};
#pragma unroll
            for (int i = 0; i < 4; i++)
#pragma unroll
                for (int j = 0; j < 4; j++)
                    acc[i][j] = fmaf(a2[i], bb2[j],
                                fmaf(a1[i], bb1[j],
                                fmaf(a0[i], bb0[j], acc[i][j])));
        }
    }

    // epilogue: bias + BN + LeakyReLU, store [b][co][t] with vec4 over t
#pragma unroll
    for (int j = 0; j < 4; j++) {
        int co = cb + c0 + j;
        float bs = bias[co];
        float scale = bn_g[co] * rsqrtf(bn_v[co] + 1e-5f);
        float shift = bn_b[co] - bn_m[co] * scale;
        float4 o;
        float y;
        y = (acc[0][j] + bs) * scale + shift; o.x = (y >= 0.f) ? y : 0.01f * y;
        y = (acc[1][j] + bs) * scale + shift; o.y = (y >= 0.f) ? y : 0.01f * y;
        y = (acc[2][j] + bs) * scale + shift; o.z = (y >= 0.f) ? y : 0.01f * y;
        y = (acc[3][j] + bs) * scale + shift; o.w = (y >= 0.f) ? y : 0.01f * y;
        *reinterpret_cast<float4*>(out + ((long)b * COUT + co) * LOUT + T0 + t0) = o;
    }
}

// ---------------- conv3: stride 1, bias only, transposed output + fused znorm ----------------
// Block tile: 128 co x 32 t. Threads 256: tx=co-group(32), ty=t-group(8), 4x4 acc.
__global__ __launch_bounds__(256) void conv3_kernel(
    const float* __restrict__ x, const float* __restrict__ wt,
    const float* __restrict__ bias,
    float* __restrict__ z, float* __restrict__ znorm)
{
    constexpr int CIN = C2, LIN = L2, CC = 16;

    __shared__ float sx[CC][40];       // sx[ci][u] = x[ci][T0+u-1], u<34
    __shared__ float sw[CC][3][128];   // sw[ci][k][co]

    const int b   = blockIdx.y;
    const int T0  = blockIdx.x * 32;
    const int tid = threadIdx.x;
    const int tx  = tid & 31;
    const int ty  = tid >> 5;
    const int t0  = ty * 4;
    const int c0  = tx * 4;

    float acc[4][4];
#pragma unroll
    for (int i = 0; i < 4; i++)
#pragma unroll
        for (int j = 0; j < 4; j++) acc[i][j] = 0.0f;

    for (int cc = 0; cc < CIN; cc += CC) {
        __syncthreads();
        const float* xb = x + ((long)b * CIN + cc) * LIN;
        for (int i = tid; i < CC * 34; i += 256) {
            int ci = i / 34, u = i - ci * 34;
            int p = T0 + u - 1;
            sx[ci][u] = (p >= 0 && p < LIN) ? xb[(long)ci * LIN + p] : 0.0f;
        }
        for (int i = tid; i < CC * 384; i += 256) {
            int q = i >> 7;                 // q = ci*3+k
            ((float*)sw)[i] = wt[(long)(cc * 3 + q) * C3 + (i & 127)];
        }
        __syncthreads();

#pragma unroll 4
        for (int ci = 0; ci < CC; ci++) {
            float4 aL = *(const float4*)&sx[ci][t0];
            float4 aH = *(const float4*)&sx[ci][t0 + 4];
            float4 b0 = *(const float4*)&sw[ci][0][c0];
            float4 b1 = *(const float4*)&sw[ci][1][c0];
            float4 b2 = *(const float4*)&sw[ci][2][c0];
            float a0[4] = {aL.x, aL.y, aL.z, aL.w};          // k=0
            float a1[4] = {aL.y, aL.z, aL.w, aH.x};          // k=1
            float a2[4] = {aL.z, aL.w, aH.x, aH.y};          // k=2
            float bb0[4] = {b0.x, b0.y, b0.z, b0.w};
            float bb1[4] = {b1.x, b1.y, b1.z, b1.w};
            float bb2[4] = {b2.x, b2.y, b2.z, b2.w};
#pragma unroll
            for (int i = 0; i < 4; i++)
#pragma unroll
                for (int j = 0; j < 4; j++)
                    acc[i][j] = fmaf(a2[i], bb2[j],
                                fmaf(a1[i], bb1[j],
                                fmaf(a0[i], bb0[j], acc[i][j])));
        }
    }

    // epilogue: bias, store z[row][co] (vec4 over co), fused row-norm
    float bs[4];
#pragma unroll
    for (int j = 0; j < 4; j++) bs[j] = bias[c0 + j];

#pragma unroll
    for (int i = 0; i < 4; i++) {
        long row = (long)b * L3 + T0 + t0 + i;
        float y0 = acc[i][0] + bs[0];
        float y1 = acc[i][1] + bs[1];
        float y2 = acc[i][2] + bs[2];
        float y3 = acc[i][3] + bs[3];
        float4 o; o.x = y0; o.y = y1; o.z = y2; o.w = y3;
        *reinterpret_cast<float4*>(z + row * C3 + c0) = o;
        float s = fmaf(y0, y0, fmaf(y1, y1, fmaf(y2, y2, y3 * y3)));
#pragma unroll
        for (int off = 16; off > 0; off >>= 1)
            s += __shfl_xor_sync(0xffffffffu, s, off);
        if (tx == 0) znorm[row] = s;
    }
}

// ---------------- embedding row squared-norm ----------------
__global__ void rownorm_kernel(const float* __restrict__ src,
                               float* __restrict__ dst, int nrows)
{
    int row  = blockIdx.x * 4 + (threadIdx.x >> 5);
    int lane = threadIdx.x & 31;
    if (row >= nrows) return;
    const float* r = src + (long)row * 128;
    float s = 0.0f;
#pragma unroll
    for (int k = 0; k < 4; k++) {
        float v = r[lane + k * 32];
        s = fmaf(v, v, s);
    }
#pragma unroll
    for (int off = 16; off > 0; off >>= 1)
        s += __shfl_xor_sync(0xffffffffu, s, off);
    if (lane == 0) dst[row] = s;
}

// ---------------- VQ: 64 rows/block, scan 4096 codes, argmin + gather ----------------
__global__ __launch_bounds__(256) void vq_kernel(const float* __restrict__ emb,
                                                 const float* __restrict__ enorm,
                                                 const float* __restrict__ z,
                                                 const float* __restrict__ znorm,
                                                 float* __restrict__ codes_out,
                                                 float* __restrict__ quant_out)
{
    __shared__ float zs[64][132];
    __shared__ float es[64][132];
    __shared__ float zns[64];
    __shared__ float ens[64];
    __shared__ int   sidx[64];

    const int tid = threadIdx.x;
    const int tx  = tid & 15;       // code dimension
    const int ty  = tid >> 4;       // row dimension
    const int M0  = blockIdx.x * 64;

    for (int i = tid; i < 64 * 32; i += 256) {
        int r = i >> 5, c = i & 31;
        *reinterpret_cast<float4*>(&zs[r][c * 4]) =
            *reinterpret_cast<const float4*>(z + (long)(M0 + r) * 128 + c * 4);
    }
    if (tid < 64) zns[tid] = znorm[M0 + tid];

    float bv[4]; int bi[4];
#pragma unroll
    for (int i = 0; i < 4; i++) { bv[i] = 3.4e38f; bi[i] = 0; }

    for (int N0 = 0; N0 < NEMB; N0 += 64) {
        __syncthreads();
        for (int i = tid; i < 64 * 32; i += 256) {
            int r = i >> 5, c = i & 31;
            *reinterpret_cast<float4*>(&es[r][c * 4]) =
                *reinterpret_cast<const float4*>(emb + (long)(N0 + r) * 128 + c * 4);
        }
        if (tid < 64) ens[tid] = enorm[N0 + tid];
        __syncthreads();

        float c[4][4];
#pragma unroll
        for (int i = 0; i < 4; i++)
#pragma unroll
            for (int j = 0; j < 4; j++) c[i][j] = 0.0f;

#pragma unroll 8
        for (int k4 = 0; k4 < 32; k4++) {
            float4 a[4], bb[4];
#pragma unroll
            for (int i = 0; i < 4; i++)
                a[i] = *reinterpret_cast<const float4*>(&zs[ty * 4 + i][k4 * 4]);
#pragma unroll
            for (int j = 0; j < 4; j++)
                bb[j] = *reinterpret_cast<const float4*>(&es[tx * 4 + j][k4 * 4]);
#pragma unroll
            for (int i = 0; i < 4; i++)
#pragma unroll
                for (int j = 0; j < 4; j++) {
                    float s = c[i][j];
                    s = fmaf(a[i].x, bb[j].x, s);
                    s = fmaf(a[i].y, bb[j].y, s);
                    s = fmaf(a[i].z, bb[j].z, s);
                    s = fmaf(a[i].w, bb[j].w, s);
                    c[i][j] = s;
                }
        }

#pragma unroll
        for (int i = 0; i < 4; i++) {
            const float zn = zns[ty * 4 + i];
#pragma unroll
            for (int j = 0; j < 4; j++) {
                float t1 = zn + ens[tx * 4 + j];
                float d  = t1 - 2.0f * c[i][j];
                if (d < bv[i]) { bv[i] = d; bi[i] = N0 + tx * 4 + j; }
            }
        }
    }

#pragma unroll
    for (int i = 0; i < 4; i++) {
#pragma unroll
        for (int off = 8; off > 0; off >>= 1) {
            float ov = __shfl_xor_sync(0xffffffffu, bv[i], off);
            int   oi = __shfl_xor_sync(0xffffffffu, bi[i], off);
            if (ov < bv[i] || (ov == bv[i] && oi < bi[i])) { bv[i] = ov; bi[i] = oi; }
        }
        if (tx == 0) sidx[ty * 4 + i] = bi[i];
    }
    __syncthreads();

    if (codes_out && tid < 64)
        codes_out[M0 + tid] = (float)sidx[tid];
    if (quant_out) {
        for (int i = tid; i < 64 * 32; i += 256) {
            int r = i >> 5, c = i & 31;
            *reinterpret_cast<float4*>(quant_out + (long)(M0 + r) * 128 + c * 4) =
                *reinterpret_cast<const float4*>(emb + (long)sidx[r] * 128 + c * 4);
        }
    }
}

// ---------------- launch ----------------
extern "C" void kernel_launch(void* const* d_in, const int* in_sizes, int n_in,
                              void* d_out, int out_size)
{
    const float* x   = (const float*)d_in[0];
    const float* w1  = (const float*)d_in[1];
    const float* b1  = (const float*)d_in[2];
    const float* g1  = (const float*)d_in[3];
    const float* be1 = (const float*)d_in[4];
    const float* m1  = (const float*)d_in[5];
    const float* v1  = (const float*)d_in[6];
    const float* w2  = (const float*)d_in[7];
    const float* b2  = (const float*)d_in[8];
    const float* g2  = (const float*)d_in[9];
    const float* be2 = (const float*)d_in[10];
    const float* m2  = (const float*)d_in[11];
    const float* v2  = (const float*)d_in[12];
    const float* w3  = (const float*)d_in[13];
    const float* b3  = (const float*)d_in[14];
    const float* emb = (const float*)d_in[15];

    float *h1, *h2, *z, *zn, *en, *wt1, *wt2, *wt3;
    cudaGetSymbolAddress((void**)&h1,  g_h1);
    cudaGetSymbolAddress((void**)&h2,  g_h2);
    cudaGetSymbolAddress((void**)&z,   g_z);
    cudaGetSymbolAddress((void**)&zn,  g_znorm);
    cudaGetSymbolAddress((void**)&en,  g_enorm);
    cudaGetSymbolAddress((void**)&wt1, g_wt1);
    cudaGetSymbolAddress((void**)&wt2, g_wt2);
    cudaGetSymbolAddress((void**)&wt3, g_wt3);

    float* codes_out = (float*)d_out;
    float* quant_out = (float*)d_out + NROWS;
    if (out_size == NROWS * C3) { codes_out = nullptr; quant_out = (float*)d_out; }
    else if (out_size == NROWS) { quant_out = nullptr; }

    // weight transposes (tiny)
    wtrans_kernel<<<(C0 * 3 * C1 + 255) / 256, 256>>>(w1, wt1, C0, C1);
    wtrans_kernel<<<(C1 * 3 * C2 + 255) / 256, 256>>>(w2, wt2, C1, C2);
    wtrans_kernel<<<(C2 * 3 * C3 + 255) / 256, 256>>>(w3, wt3, C2, C3);

    // encoder
    conv_s2_kernel<C0, C1, L0>
        <<<dim3(L1 / 64, C1 / 64, BATCH), 256>>>(x, wt1, b1, g1, be1, m1, v1, h1);
    conv_s2_kernel<C1, C2, L1>
        <<<dim3(L2 / 64, C2 / 64, BATCH), 256>>>(h1, wt2, b2, g2, be2, m2, v2, h2);
    conv3_kernel<<<dim3(L3 / 32, BATCH), 256>>>(h2, wt3, b3, z, zn);

    // codebook norms
    rownorm_kernel<<<NEMB / 4, 128>>>(emb, en, NEMB);

    // VQ argmin + gather
    vq_kernel<<<NROWS / 64, 256>>>(emb, en, z, zn, codes_out, quant_out);
}

// round 10
// speedup vs baseline: 1.9099x; 1.3994x over previous
#include <cuda_runtime.h>
#include <cuda_bf16.h>
#include <math.h>

// ---------------- problem constants ----------------
#define BATCH 32
#define L0    4096
#define C0    256
#define C1    256
#define C2    512
#define C3    128          // EMB_DIM
#define L1    2048
#define L2    1024
#define L3    1024
#define NEMB  4096
#define NROWS (BATCH * L3) // 32768

// ---------------- scratch ----------------
__device__ float g_h1[BATCH * C1 * L1];     // 64 MB
__device__ float g_h2[BATCH * C2 * L2];     // 64 MB
__device__ float g_z [NROWS * C3];          // 16 MB
__device__ float g_znorm[NROWS];
__device__ float g_enorm[NEMB];
__device__ float g_wt1[C0 * 3 * C1];        // transposed weights [(ci*3+k)][co]
__device__ float g_wt2[C1 * 3 * C2];
__device__ float g_wt3[C2 * 3 * C3];

// ---------------- weight transpose: w[co][ci][k] -> wt[(ci*3+k)][co] ----------------
__global__ void wtrans_kernel(const float* __restrict__ w, float* __restrict__ wt,
                              int CIN, int COUT)
{
    int idx = blockIdx.x * 256 + threadIdx.x;
    int total = CIN * 3 * COUT;
    if (idx < total) {
        int co = idx % COUT;
        int r  = idx / COUT;            // r = ci*3+k
        wt[idx] = w[(long)co * CIN * 3 + r];
    }
}

// ---------------- stride-2 conv + BN(eval) + LeakyReLU ----------------
// Block tile: 64 co x 128 t. 256 threads: tx=co-group(16), ty=t-group(16), 4co x 8t acc.
// x staged de-interleaved (evens/odds): taps contiguous in t; a-loads broadcast per ty.
template<int CIN, int COUT, int LIN>
__global__ __launch_bounds__(256) void conv_s2_kernel(
    const float* __restrict__ x, const float* __restrict__ wt,
    const float* __restrict__ bias, const float* __restrict__ bn_g,
    const float* __restrict__ bn_b, const float* __restrict__ bn_m,
    const float* __restrict__ bn_v, float* __restrict__ out)
{
    constexpr int LOUT = LIN / 2;
    constexpr int CC   = 16;
    constexpr int TT   = 128;

    __shared__ float ev[CC][132];     // ev[ci][u] = x[ci][2*(T0+u)]    u<128
    __shared__ float od[CC][132];     // od[ci][u] = x[ci][2*(T0+u)-1]  u<129
    __shared__ float sw[CC][3][64];   // sw[ci][k][co]

    const int b   = blockIdx.z;
    const int cb  = blockIdx.y * 64;
    const int T0  = blockIdx.x * TT;
    const int tid = threadIdx.x;
    const int tx  = tid & 15;
    const int ty  = tid >> 4;
    const int t0  = ty * 8;
    const int c0  = tx * 4;

    float acc[8][4];
#pragma unroll
    for (int i = 0; i < 8; i++)
#pragma unroll
        for (int j = 0; j < 4; j++) acc[i][j] = 0.0f;

    for (int cc = 0; cc < CIN; cc += CC) {
        __syncthreads();
        const float* xb = x + ((long)b * CIN + cc) * LIN;
        for (int i = tid; i < CC * TT; i += 256) {
            int ci = i >> 7, u = i & 127;
            ev[ci][u] = xb[(long)ci * LIN + 2 * (T0 + u)];
        }
        for (int i = tid; i < CC * 129; i += 256) {
            int ci = i / 129, u = i - ci * 129;
            int p = 2 * (T0 + u) - 1;
            od[ci][u] = (p >= 0) ? xb[(long)ci * LIN + p] : 0.0f;
        }
        for (int i = tid; i < CC * 192; i += 256) {
            int q = i >> 6;                 // q = ci*3+k
            ((float*)sw)[i] = wt[(long)(cc * 3 + q) * COUT + cb + (i & 63)];
        }
        __syncthreads();

#pragma unroll 4
        for (int ci = 0; ci < CC; ci++) {
            float4 e0 = *(const float4*)&ev[ci][t0];
            float4 e1 = *(const float4*)&ev[ci][t0 + 4];
            float4 o0 = *(const float4*)&od[ci][t0];
            float4 o1 = *(const float4*)&od[ci][t0 + 4];
            float  oX = od[ci][t0 + 8];
            float4 b0 = *(const float4*)&sw[ci][0][c0];
            float4 b1 = *(const float4*)&sw[ci][1][c0];
            float4 b2 = *(const float4*)&sw[ci][2][c0];
            float a0[8] = {o0.x, o0.y, o0.z, o0.w, o1.x, o1.y, o1.z, o1.w};  // k=0
            float a1[8] = {e0.x, e0.y, e0.z, e0.w, e1.x, e1.y, e1.z, e1.w};  // k=1
            float a2[8] = {o0.y, o0.z, o0.w, o1.x, o1.y, o1.z, o1.w, oX};    // k=2
            float bb0[4] = {b0.x, b0.y, b0.z, b0.w};
            float bb1[4] = {b1.x, b1.y, b1.z, b1.w};
            float bb2[4] = {b2.x, b2.y, b2.z, b2.w};
#pragma unroll
            for (int i = 0; i < 8; i++)
#pragma unroll
                for (int j = 0; j < 4; j++)
                    acc[i][j] = fmaf(a2[i], bb2[j],
                                fmaf(a1[i], bb1[j],
                                fmaf(a0[i], bb0[j], acc[i][j])));
        }
    }

    // epilogue: bias + BN + LeakyReLU, store [b][co][t] with 2x vec4 over t
#pragma unroll
    for (int j = 0; j < 4; j++) {
        int co = cb + c0 + j;
        float bs = bias[co];
        float scale = bn_g[co] * rsqrtf(bn_v[co] + 1e-5f);
        float shift = bn_b[co] - bn_m[co] * scale;
        float* orow = out + ((long)b * COUT + co) * LOUT + T0 + t0;
#pragma unroll
        for (int h = 0; h < 2; h++) {
            float4 o;
            float y;
            y = (acc[h*4+0][j] + bs) * scale + shift; o.x = (y >= 0.f) ? y : 0.01f * y;
            y = (acc[h*4+1][j] + bs) * scale + shift; o.y = (y >= 0.f) ? y : 0.01f * y;
            y = (acc[h*4+2][j] + bs) * scale + shift; o.z = (y >= 0.f) ? y : 0.01f * y;
            y = (acc[h*4+3][j] + bs) * scale + shift; o.w = (y >= 0.f) ? y : 0.01f * y;
            *reinterpret_cast<float4*>(orow + h * 4) = o;
        }
    }
}

// ---------------- conv3: stride 1, bias only, transposed output + fused znorm ----------------
// Block tile: 128 co x 64 t. 256 threads: tx=co-group(32), ty=t-group(8), 4co x 8t acc.
__global__ __launch_bounds__(256) void conv3_kernel(
    const float* __restrict__ x, const float* __restrict__ wt,
    const float* __restrict__ bias,
    float* __restrict__ z, float* __restrict__ znorm)
{
    constexpr int CIN = C2, LIN = L2, CC = 16;

    __shared__ float sx[CC][76];       // sx[ci][u] = x[ci][T0+u-1], u<66
    __shared__ float sw[CC][3][128];   // sw[ci][k][co]

    const int b   = blockIdx.y;
    const int T0  = blockIdx.x * 64;
    const int tid = threadIdx.x;
    const int tx  = tid & 31;
    const int ty  = tid >> 5;
    const int t0  = ty * 8;
    const int c0  = tx * 4;

    float acc[8][4];
#pragma unroll
    for (int i = 0; i < 8; i++)
#pragma unroll
        for (int j = 0; j < 4; j++) acc[i][j] = 0.0f;

    for (int cc = 0; cc < CIN; cc += CC) {
        __syncthreads();
        const float* xb = x + ((long)b * CIN + cc) * LIN;
        for (int i = tid; i < CC * 66; i += 256) {
            int ci = i / 66, u = i - ci * 66;
            int p = T0 + u - 1;
            sx[ci][u] = (p >= 0 && p < LIN) ? xb[(long)ci * LIN + p] : 0.0f;
        }
        for (int i = tid; i < CC * 384; i += 256) {
            int q = i >> 7;                 // q = ci*3+k
            ((float*)sw)[i] = wt[(long)(cc * 3 + q) * C3 + (i & 127)];
        }
        __syncthreads();

#pragma unroll 4
        for (int ci = 0; ci < CC; ci++) {
            float4 s0 = *(const float4*)&sx[ci][t0];
            float4 s1 = *(const float4*)&sx[ci][t0 + 4];
            float4 s2 = *(const float4*)&sx[ci][t0 + 8];   // uses .x,.y
            float4 b0 = *(const float4*)&sw[ci][0][c0];
            float4 b1 = *(const float4*)&sw[ci][1][c0];
            float4 b2 = *(const float4*)&sw[ci][2][c0];
            float a0[8] = {s0.x, s0.y, s0.z, s0.w, s1.x, s1.y, s1.z, s1.w};       // k=0
            float a1[8] = {s0.y, s0.z, s0.w, s1.x, s1.y, s1.z, s1.w, s2.x};       // k=1
            float a2[8] = {s0.z, s0.w, s1.x, s1.y, s1.z, s1.w, s2.x, s2.y};       // k=2
            float bb0[4] = {b0.x, b0.y, b0.z, b0.w};
            float bb1[4] = {b1.x, b1.y, b1.z, b1.w};
            float bb2[4] = {b2.x, b2.y, b2.z, b2.w};
#pragma unroll
            for (int i = 0; i < 8; i++)
#pragma unroll
                for (int j = 0; j < 4; j++)
                    acc[i][j] = fmaf(a2[i], bb2[j],
                                fmaf(a1[i], bb1[j],
                                fmaf(a0[i], bb0[j], acc[i][j])));
        }
    }

    // epilogue: bias, store z[row][co] (vec4 over co), fused row-norm (warp = one ty)
    float bs[4];
#pragma unroll
    for (int j = 0; j < 4; j++) bs[j] = bias[c0 + j];

#pragma unroll
    for (int i = 0; i < 8; i++) {
        long row = (long)b * L3 + T0 + t0 + i;
        float y0 = acc[i][0] + bs[0];
        float y1 = acc[i][1] + bs[1];
        float y2 = acc[i][2] + bs[2];
        float y3 = acc[i][3] + bs[3];
        float4 o; o.x = y0; o.y = y1; o.z = y2; o.w = y3;
        *reinterpret_cast<float4*>(z + row * C3 + c0) = o;
        float s = fmaf(y0, y0, fmaf(y1, y1, fmaf(y2, y2, y3 * y3)));
#pragma unroll
        for (int off = 16; off > 0; off >>= 1)
            s += __shfl_xor_sync(0xffffffffu, s, off);
        if (tx == 0) znorm[row] = s;
    }
}

// ---------------- embedding row squared-norm ----------------
__global__ void rownorm_kernel(const float* __restrict__ src,
                               float* __restrict__ dst, int nrows)
{
    int row  = blockIdx.x * 4 + (threadIdx.x >> 5);
    int lane = threadIdx.x & 31;
    if (row >= nrows) return;
    const float* r = src + (long)row * 128;
    float s = 0.0f;
#pragma unroll
    for (int k = 0; k < 4; k++) {
        float v = r[lane + k * 32];
        s = fmaf(v, v, s);
    }
#pragma unroll
    for (int off = 16; off > 0; off >>= 1)
        s += __shfl_xor_sync(0xffffffffu, s, off);
    if (lane == 0) dst[row] = s;
}

// ---------------- VQ: 128 rows/block, scan 4096 codes, argmin + gather ----------------
// 256 threads: tx=code-group(16, 4 codes), ty=row-group(16, 8 rows).
__global__ __launch_bounds__(256) void vq_kernel(const float* __restrict__ emb,
                                                 const float* __restrict__ enorm,
                                                 const float* __restrict__ z,
                                                 const float* __restrict__ znorm,
                                                 float* __restrict__ codes_out,
                                                 float* __restrict__ quant_out)
{
    __shared__ float zs[128][132];
    __shared__ float es[64][132];
    __shared__ float zns[128];
    __shared__ float ens[64];
    __shared__ int   sidx[128];

    const int tid = threadIdx.x;
    const int tx  = tid & 15;       // code dimension
    const int ty  = tid >> 4;       // row dimension
    const int M0  = blockIdx.x * 128;

    for (int i = tid; i < 128 * 32; i += 256) {
        int r = i >> 5, c = i & 31;
        *reinterpret_cast<float4*>(&zs[r][c * 4]) =
            *reinterpret_cast<const float4*>(z + (long)(M0 + r) * 128 + c * 4);
    }
    if (tid < 128) zns[tid] = znorm[M0 + tid];

    float bv[8]; int bi[8];
#pragma unroll
    for (int i = 0; i < 8; i++) { bv[i] = 3.4e38f; bi[i] = 0; }

    for (int N0 = 0; N0 < NEMB; N0 += 64) {
        __syncthreads();
        for (int i = tid; i < 64 * 32; i += 256) {
            int r = i >> 5, c = i & 31;
            *reinterpret_cast<float4*>(&es[r][c * 4]) =
                *reinterpret_cast<const float4*>(emb + (long)(N0 + r) * 128 + c * 4);
        }
        if (tid < 64) ens[tid] = enorm[N0 + tid];
        __syncthreads();

        float c[8][4];
#pragma unroll
        for (int i = 0; i < 8; i++)
#pragma unroll
            for (int j = 0; j < 4; j++) c[i][j] = 0.0f;

#pragma unroll 4
        for (int k4 = 0; k4 < 32; k4++) {
            float4 a[8], bb[4];
#pragma unroll
            for (int i = 0; i < 8; i++)
                a[i] = *reinterpret_cast<const float4*>(&zs[ty * 8 + i][k4 * 4]);
#pragma unroll
            for (int j = 0; j < 4; j++)
                bb[j] = *reinterpret_cast<const float4*>(&es[tx * 4 + j][k4 * 4]);
#pragma unroll
            for (int i = 0; i < 8; i++)
#pragma unroll
                for (int j = 0; j < 4; j++) {
                    float s = c[i][j];
                    s = fmaf(a[i].x, bb[j].x, s);
                    s = fmaf(a[i].y, bb[j].y, s);
                    s = fmaf(a[i].z, bb[j].z, s);
                    s = fmaf(a[i].w, bb[j].w, s);
                    c[i][j] = s;
                }
        }

#pragma unroll
        for (int i = 0; i < 8; i++) {
            const float zn = zns[ty * 8 + i];
#pragma unroll
            for (int j = 0; j < 4; j++) {
                float t1 = zn + ens[tx * 4 + j];
                float d  = t1 - 2.0f * c[i][j];
                if (d < bv[i]) { bv[i] = d; bi[i] = N0 + tx * 4 + j; }
            }
        }
    }

    // reduce across the 16 tx lanes sharing each row (within 16-lane half-warp)
#pragma unroll
    for (int i = 0; i < 8; i++) {
#pragma unroll
        for (int off = 8; off > 0; off >>= 1) {
            float ov = __shfl_xor_sync(0xffffffffu, bv[i], off);
            int   oi = __shfl_xor_sync(0xffffffffu, bi[i], off);
            if (ov < bv[i] || (ov == bv[i] && oi < bi[i])) { bv[i] = ov; bi[i] = oi; }
        }
        if (tx == 0) sidx[ty * 8 + i] = bi[i];
    }
    __syncthreads();

    if (codes_out && tid < 128)
        codes_out[M0 + tid] = (float)sidx[tid];
    if (quant_out) {
        for (int i = tid; i < 128 * 32; i += 256) {
            int r = i >> 5, c = i & 31;
            *reinterpret_cast<float4*>(quant_out + (long)(M0 + r) * 128 + c * 4) =
                *reinterpret_cast<const float4*>(emb + (long)sidx[r] * 128 + c * 4);
        }
    }
}

// ---------------- launch ----------------
extern "C" void kernel_launch(void* const* d_in, const int* in_sizes, int n_in,
                              void* d_out, int out_size)
{
    const float* x   = (const float*)d_in[0];
    const float* w1  = (const float*)d_in[1];
    const float* b1  = (const float*)d_in[2];
    const float* g1  = (const float*)d_in[3];
    const float* be1 = (const float*)d_in[4];
    const float* m1  = (const float*)d_in[5];
    const float* v1  = (const float*)d_in[6];
    const float* w2  = (const float*)d_in[7];
    const float* b2  = (const float*)d_in[8];
    const float* g2  = (const float*)d_in[9];
    const float* be2 = (const float*)d_in[10];
    const float* m2  = (const float*)d_in[11];
    const float* v2  = (const float*)d_in[12];
    const float* w3  = (const float*)d_in[13];
    const float* b3  = (const float*)d_in[14];
    const float* emb = (const float*)d_in[15];

    float *h1, *h2, *z, *zn, *en, *wt1, *wt2, *wt3;
    cudaGetSymbolAddress((void**)&h1,  g_h1);
    cudaGetSymbolAddress((void**)&h2,  g_h2);
    cudaGetSymbolAddress((void**)&z,   g_z);
    cudaGetSymbolAddress((void**)&zn,  g_znorm);
    cudaGetSymbolAddress((void**)&en,  g_enorm);
    cudaGetSymbolAddress((void**)&wt1, g_wt1);
    cudaGetSymbolAddress((void**)&wt2, g_wt2);
    cudaGetSymbolAddress((void**)&wt3, g_wt3);

    float* codes_out = (float*)d_out;
    float* quant_out = (float*)d_out + NROWS;
    if (out_size == NROWS * C3) { codes_out = nullptr; quant_out = (float*)d_out; }
    else if (out_size == NROWS) { quant_out = nullptr; }

    // weight transposes (tiny)
    wtrans_kernel<<<(C0 * 3 * C1 + 255) / 256, 256>>>(w1, wt1, C0, C1);
    wtrans_kernel<<<(C1 * 3 * C2 + 255) / 256, 256>>>(w2, wt2, C1, C2);
    wtrans_kernel<<<(C2 * 3 * C3 + 255) / 256, 256>>>(w3, wt3, C2, C3);

    // encoder
    conv_s2_kernel<C0, C1, L0>
        <<<dim3(L1 / 128, C1 / 64, BATCH), 256>>>(x, wt1, b1, g1, be1, m1, v1, h1);
    conv_s2_kernel<C1, C2, L1>
        <<<dim3(L2 / 128, C2 / 64, BATCH), 256>>>(h1, wt2, b2, g2, be2, m2, v2, h2);
    conv3_kernel<<<dim3(L3 / 64, BATCH), 256>>>(h2, wt3, b3, z, zn);

    // codebook norms
    rownorm_kernel<<<NEMB / 4, 128>>>(emb, en, NEMB);

    // VQ argmin + gather
    vq_kernel<<<NROWS / 128, 256>>>(emb, en, z, zn, codes_out, quant_out);
}